// round 3
// baseline (speedup 1.0000x reference)
#include <cuda_runtime.h>
#include <stdint.h>

#define VGRID   64
#define G3      (VGRID * VGRID * VGRID)       // 262144
#define BMAX    8
#define CCH     96
#define NMAX    (BMAX * 131072)               // 1048576

// Scratch (zero-initialized at module load; kernels maintain the zero
// invariant across graph replays — see finalize/zero_counts).
__device__ float g_scratch[(size_t)BMAX * G3 * CCH];  // [B*G3][96] channel-contig
__device__ int   g_counts[BMAX * G3];
__device__ int   g_seg[NMAX];

// ---------------------------------------------------------------------------
// Kernel 1: per-point voxel/segment index + count accumulation.
// XLA folds the reference's `coord / 0.02` into `coord * 50.0f` (reciprocal
// of 0.02 is exactly representable), so we MUST multiply by 50.0f, not divide
// by 0.02f — the two differ by ~2e-8 relative and flip floor() for a handful
// of boundary points (the deterministic rel_err=1.337e-3 seen in R1/R2).
// ---------------------------------------------------------------------------
__global__ void voxel_index_kernel(const float* __restrict__ coord,
                                   const int*   __restrict__ offset,
                                   const int*   __restrict__ resolution,
                                   int n, int nb) {
    int p = blockIdx.x * blockDim.x + threadIdx.x;
    if (p >= n) return;

    // searchsorted(offset, p, side='right') = #(offset[i] <= p)
    int b = 0;
    #pragma unroll
    for (int i = 0; i < BMAX; i++) {
        if (i < nb && offset[i] <= p) b++;
    }

    float fx = coord[3 * p + 0];
    float fy = coord[3 * p + 1];
    float fz = coord[3 * p + 2];

    // Reference (after XLA folding): vox = floor(coord * 50.0f)
    float vx = floorf(fx * 50.0f);
    float vy = floorf(fy * 50.0f);
    float vz = floorf(fz * 50.0f);
    // gidx = floor(vox / (cur_res / 64)); divisor is runtime data -> rn division
    float cr = (float)(resolution[b] + 1);
    float sc = __fdiv_rn(cr, (float)VGRID);
    int gx = (int)floorf(__fdiv_rn(vx, sc));
    int gy = (int)floorf(__fdiv_rn(vy, sc));
    int gz = (int)floorf(__fdiv_rn(vz, sc));
    gx = min(max(gx, 0), VGRID - 1);
    gy = min(max(gy, 0), VGRID - 1);
    gz = min(max(gz, 0), VGRID - 1);

    // Scratch spatial order matches OUTPUT spatial order: (z, y, x), x fastest.
    int sp  = (gz * VGRID + gy) * VGRID + gx;
    int seg = b * G3 + sp;
    g_seg[p] = seg;
    atomicAdd(&g_counts[seg], 1);
}

// ---------------------------------------------------------------------------
// Kernel 2: feature accumulation. 8 threads per point, 3 x float4 each.
// Coalesced 128B feat reads; vectorized global reductions (red.v4.f32).
// ---------------------------------------------------------------------------
__global__ void accumulate_kernel(const float* __restrict__ feat, int n) {
    int idx = blockIdx.x * blockDim.x + threadIdx.x;
    int p = idx >> 3;          // point
    int g = idx & 7;           // float4 group base within the 24 groups
    if (p >= n) return;

    int seg = g_seg[p];
    const float4* __restrict__ frow = (const float4*)(feat + (size_t)p * CCH);
    float* dst = g_scratch + (size_t)seg * CCH;

    #pragma unroll
    for (int k = 0; k < 3; k++) {
        int q = g + 8 * k;                 // group 0..23
        float4 v = frow[q];
        asm volatile(
            "red.global.add.v4.f32 [%0], {%1, %2, %3, %4};"
            :: "l"(dst + 4 * q), "f"(v.x), "f"(v.y), "f"(v.z), "f"(v.w)
            : "memory");
    }
}

// ---------------------------------------------------------------------------
// Kernel 3: normalize + transpose (spatial-x <-> channel) + lazy scratch zero.
// Block = 32x32. blockIdx: x = spatial tile (8192), y = channel tile (3), z = b.
// out[b][c][z][y][x] = scratch[b][(z,y,x)][c] / max(cnt,1)
// ---------------------------------------------------------------------------
__global__ void finalize_kernel(float* __restrict__ out) {
    __shared__ float tile[32][33];
    int b  = blockIdx.z;
    int c0 = blockIdx.y * 32;
    int s0 = blockIdx.x * 32;
    int tx = threadIdx.x;
    int ty = threadIdx.y;

    // Load phase: row = spatial (s0+ty), col = channel (c0+tx). Coalesced reads.
    int s   = s0 + ty;
    int cnt = g_counts[b * G3 + s];
    float v = 0.0f;
    size_t sidx = ((size_t)(b * G3 + s)) * CCH + (c0 + tx);
    if (cnt > 0) {
        v = __fdiv_rn(g_scratch[sidx], (float)cnt);
        g_scratch[sidx] = 0.0f;   // re-establish zero invariant for next replay
    }
    tile[ty][tx] = v;
    __syncthreads();

    // Write phase: row = channel (c0+ty), col = spatial x (s0+tx). Coalesced.
    size_t o = ((size_t)(b * CCH + c0 + ty)) * G3 + (s0 + tx);
    out[o] = tile[tx][ty];
}

// ---------------------------------------------------------------------------
// Kernel 4: zero counts for next replay (must run after finalize reads them).
// ---------------------------------------------------------------------------
__global__ void zero_counts_kernel(int total) {
    int i = blockIdx.x * blockDim.x + threadIdx.x;
    if (i < total) g_counts[i] = 0;
}

// ---------------------------------------------------------------------------
extern "C" void kernel_launch(void* const* d_in, const int* in_sizes, int n_in,
                              void* d_out, int out_size) {
    const float* coord      = (const float*)d_in[0];
    const float* feat       = (const float*)d_in[1];
    const int*   offset     = (const int*)d_in[2];
    const int*   resolution = (const int*)d_in[3];
    float*       out        = (float*)d_out;

    int n  = in_sizes[0] / 3;   // number of points
    int nb = in_sizes[2];       // number of batches

    voxel_index_kernel<<<(n + 255) / 256, 256>>>(coord, offset, resolution, n, nb);

    int acc_threads = n * 8;
    accumulate_kernel<<<(acc_threads + 255) / 256, 256>>>(feat, n);

    dim3 grid_f(G3 / 32, CCH / 32, nb);
    finalize_kernel<<<grid_f, dim3(32, 32)>>>(out);

    int total_counts = nb * G3;
    zero_counts_kernel<<<(total_counts + 255) / 256, 256>>>(total_counts);
}

// round 4
// speedup vs baseline: 1.2948x; 1.2948x over previous
#include <cuda_runtime.h>
#include <stdint.h>

#define VGRID   64
#define G3      (VGRID * VGRID * VGRID)       // 262144
#define BMAX    8
#define CCH     96

// Per-batch scratch (100.7 MB — fits in GB300's 126 MB L2). Zero at module
// load; finalize re-zeroes touched entries each batch, preserving the
// invariant across batches and graph replays.
__device__ float g_scratch[(size_t)G3 * CCH];
__device__ int   g_counts[BMAX * G3];         // zeroed once per replay at end

// ---------------------------------------------------------------------------
// Fused per-batch index + accumulate.
// Block = 256 threads handles 32 points. Warp 0 computes the 32 voxel ids
// (coord -> floor(c*50) -> /(cur_res/64), clamp) into smem + bumps counts;
// then 8 threads/point issue 3x red.global.add.v4.f32 into the L2-resident
// scratch. feat reads use streaming hint so they don't evict scratch.
// NOTE: *50.0f (not /0.02f) is load-bearing — XLA folds the reference's
// constant division into a multiply; dividing flips floor() at boundaries.
// ---------------------------------------------------------------------------
__global__ void fused_accum_kernel(const float* __restrict__ coord,
                                   const float* __restrict__ feat,
                                   const int*   __restrict__ offset,
                                   const int*   __restrict__ resolution,
                                   int b) {
    __shared__ int s_sp[32];
    int start = (b == 0) ? 0 : offset[b - 1];
    int end   = offset[b];
    float cr  = (float)(resolution[b] + 1);
    float sc  = __fdiv_rn(cr, (float)VGRID);

    for (int chunk = blockIdx.x;; chunk += gridDim.x) {
        int P0 = start + chunk * 32;
        if (P0 >= end) break;

        if (threadIdx.x < 32) {
            int p  = P0 + threadIdx.x;
            int sp = -1;
            if (p < end) {
                float fx = coord[3 * p + 0];
                float fy = coord[3 * p + 1];
                float fz = coord[3 * p + 2];
                float vx = floorf(fx * 50.0f);
                float vy = floorf(fy * 50.0f);
                float vz = floorf(fz * 50.0f);
                int gx = (int)floorf(__fdiv_rn(vx, sc));
                int gy = (int)floorf(__fdiv_rn(vy, sc));
                int gz = (int)floorf(__fdiv_rn(vz, sc));
                gx = min(max(gx, 0), VGRID - 1);
                gy = min(max(gy, 0), VGRID - 1);
                gz = min(max(gz, 0), VGRID - 1);
                sp = (gz * VGRID + gy) * VGRID + gx;   // output spatial order
                atomicAdd(&g_counts[b * G3 + sp], 1);
            }
            s_sp[threadIdx.x] = sp;
        }
        __syncthreads();

        int pl = threadIdx.x >> 3;    // local point 0..31
        int g  = threadIdx.x & 7;     // float4 group base
        int sp = s_sp[pl];
        if (sp >= 0) {
            const float4* __restrict__ frow =
                (const float4*)(feat + (size_t)(P0 + pl) * CCH);
            float* dst = g_scratch + (size_t)sp * CCH;
            #pragma unroll
            for (int k = 0; k < 3; k++) {
                int q = g + 8 * k;                  // 0..23
                float4 v = __ldcs(frow + q);        // streaming read
                asm volatile(
                    "red.global.add.v4.f32 [%0], {%1, %2, %3, %4};"
                    :: "l"(dst + 4 * q), "f"(v.x), "f"(v.y), "f"(v.z), "f"(v.w)
                    : "memory");
            }
        }
        __syncthreads();   // protect s_sp reuse across chunk iterations
    }
}

// ---------------------------------------------------------------------------
// Per-batch normalize + transpose (spatial-x <-> channel) + lazy scratch zero.
// Block 32x32; blockIdx.x = spatial tile (8192), blockIdx.y = channel tile (3).
// out[b][c][z][y][x] = scratch[(z,y,x)][c] / max(cnt,1); streaming store.
// ---------------------------------------------------------------------------
__global__ void finalize_kernel(float* __restrict__ out, int b) {
    __shared__ float tile[32][33];
    int c0 = blockIdx.y * 32;
    int s0 = blockIdx.x * 32;
    int tx = threadIdx.x;
    int ty = threadIdx.y;

    int s   = s0 + ty;
    int cnt = g_counts[b * G3 + s];
    float v = 0.0f;
    size_t sidx = (size_t)s * CCH + (c0 + tx);
    if (cnt > 0) {
        v = __fdiv_rn(g_scratch[sidx], (float)cnt);
        g_scratch[sidx] = 0.0f;   // re-establish zero invariant for next batch
    }
    tile[ty][tx] = v;
    __syncthreads();

    size_t o = ((size_t)(b * CCH + c0 + ty)) * G3 + (s0 + tx);
    __stcs(out + o, tile[tx][ty]);   // streaming write: don't evict scratch
}

// ---------------------------------------------------------------------------
// Zero all counts once per replay (after every batch's finalize has read them).
// ---------------------------------------------------------------------------
__global__ void zero_counts_kernel(int total) {
    int i = blockIdx.x * blockDim.x + threadIdx.x;
    if (i < total) g_counts[i] = 0;
}

// ---------------------------------------------------------------------------
extern "C" void kernel_launch(void* const* d_in, const int* in_sizes, int n_in,
                              void* d_out, int out_size) {
    const float* coord      = (const float*)d_in[0];
    const float* feat       = (const float*)d_in[1];
    const int*   offset     = (const int*)d_in[2];
    const int*   resolution = (const int*)d_in[3];
    float*       out        = (float*)d_out;

    int n  = in_sizes[0] / 3;
    int nb = in_sizes[2];
    if (nb > BMAX) nb = BMAX;

    // Enough blocks for one pass over a uniform batch; grid-stride handles
    // any actual per-batch sizes read from offset[] on device.
    int acc_blocks = ((n / nb) + 31) / 32;
    if (acc_blocks < 148) acc_blocks = 148;

    dim3 grid_f(G3 / 32, CCH / 32);
    for (int b = 0; b < nb; b++) {
        fused_accum_kernel<<<acc_blocks, 256>>>(coord, feat, offset, resolution, b);
        finalize_kernel<<<grid_f, dim3(32, 32)>>>(out, b);
    }

    int total_counts = nb * G3;
    zero_counts_kernel<<<(total_counts + 255) / 256, 256>>>(total_counts);
}

// round 5
// speedup vs baseline: 1.3048x; 1.0077x over previous
#include <cuda_runtime.h>
#include <stdint.h>

#define VGRID   64
#define G3      (VGRID * VGRID * VGRID)       // 262144
#define BMAX    8
#define CCH     96

// Per-batch scratch (100.7 MB — fits in GB300's 126 MB L2). Zero at module
// load; finalize re-zeroes touched entries each batch, preserving the
// invariant across batches and graph replays.
__device__ float g_scratch[(size_t)G3 * CCH];
__device__ int   g_counts[BMAX * G3];         // zeroed inside finalize

// ---------------------------------------------------------------------------
// Fused per-batch index + accumulate.
// Block = 256 threads handles 32 points. Warp 0 computes the 32 voxel ids
// into smem + bumps counts; then 8 threads/point issue 3x
// red.global.add.v4.f32 into the L2-resident scratch.
// NOTE: *50.0f (not /0.02f) is load-bearing — XLA folds the reference's
// constant division into a multiply; dividing flips floor() at boundaries.
// ---------------------------------------------------------------------------
__global__ void fused_accum_kernel(const float* __restrict__ coord,
                                   const float* __restrict__ feat,
                                   const int*   __restrict__ offset,
                                   const int*   __restrict__ resolution,
                                   int b) {
    __shared__ int s_sp[32];
    int start = (b == 0) ? 0 : offset[b - 1];
    int end   = offset[b];
    float cr  = (float)(resolution[b] + 1);
    float sc  = __fdiv_rn(cr, (float)VGRID);

    for (int chunk = blockIdx.x;; chunk += gridDim.x) {
        int P0 = start + chunk * 32;
        if (P0 >= end) break;

        if (threadIdx.x < 32) {
            int p  = P0 + threadIdx.x;
            int sp = -1;
            if (p < end) {
                float fx = coord[3 * p + 0];
                float fy = coord[3 * p + 1];
                float fz = coord[3 * p + 2];
                float vx = floorf(fx * 50.0f);
                float vy = floorf(fy * 50.0f);
                float vz = floorf(fz * 50.0f);
                int gx = (int)floorf(__fdiv_rn(vx, sc));
                int gy = (int)floorf(__fdiv_rn(vy, sc));
                int gz = (int)floorf(__fdiv_rn(vz, sc));
                gx = min(max(gx, 0), VGRID - 1);
                gy = min(max(gy, 0), VGRID - 1);
                gz = min(max(gz, 0), VGRID - 1);
                sp = (gz * VGRID + gy) * VGRID + gx;   // output spatial order
                atomicAdd(&g_counts[b * G3 + sp], 1);
            }
            s_sp[threadIdx.x] = sp;
        }
        __syncthreads();

        int pl = threadIdx.x >> 3;    // local point 0..31
        int g  = threadIdx.x & 7;     // float4 group base
        int sp = s_sp[pl];
        if (sp >= 0) {
            const float4* __restrict__ frow =
                (const float4*)(feat + (size_t)(P0 + pl) * CCH);
            float* dst = g_scratch + (size_t)sp * CCH;
            #pragma unroll
            for (int k = 0; k < 3; k++) {
                int q = g + 8 * k;                  // 0..23
                float4 v = __ldcs(frow + q);        // streaming read
                asm volatile(
                    "red.global.add.v4.f32 [%0], {%1, %2, %3, %4};"
                    :: "l"(dst + 4 * q), "f"(v.x), "f"(v.y), "f"(v.z), "f"(v.w)
                    : "memory");
            }
        }
        __syncthreads();   // protect s_sp reuse across chunk iterations
    }
}

// ---------------------------------------------------------------------------
// Finalize v2: 256 threads per block, tile = 32 spatial rows x 96 channels.
// 12 elements/thread (3 float4 loads, 12 scalar transposed stores) for ILP;
// per-ROW reciprocal instead of per-element division; empty rows (cnt==0)
// are neither read nor written back (scratch zero-invariant guarantees 0);
// counts zeroed in-place (folds the old zero_counts kernel).
// out[b][c][z][y][x] = scratch[(z,y,x)][c] * (1/cnt)
// ---------------------------------------------------------------------------
#define FSTRIDE 97   // odd stride -> conflict-free transpose read phase

__global__ void finalize_kernel(float* __restrict__ out, int b) {
    __shared__ float tile[32 * FSTRIDE];
    __shared__ float s_rinv[32];
    __shared__ int   s_cnt[32];

    int s0  = blockIdx.x * 32;
    int tid = threadIdx.x;

    if (tid < 32) {
        int cnt = g_counts[b * G3 + s0 + tid];
        s_cnt[tid]  = cnt;
        s_rinv[tid] = (cnt > 0) ? __fdiv_rn(1.0f, (float)cnt) : 0.0f;
        g_counts[b * G3 + s0 + tid] = 0;   // reset for next replay
    }
    __syncthreads();

    // Load phase: 768 float4 per tile; thread t handles f = t, t+256, t+512.
    #pragma unroll
    for (int k = 0; k < 3; k++) {
        int f  = tid + k * 256;
        int r  = f / 24;          // spatial row in tile (0..31)
        int cq = f % 24;          // float4 index within row (0..23)
        float4 v = make_float4(0.f, 0.f, 0.f, 0.f);
        if (s_cnt[r] > 0) {
            float4* p = (float4*)(g_scratch + (size_t)(s0 + r) * CCH) + cq;
            v = *p;
            *p = make_float4(0.f, 0.f, 0.f, 0.f);  // re-zero only touched rows
            float rinv = s_rinv[r];
            v.x *= rinv; v.y *= rinv; v.z *= rinv; v.w *= rinv;
        }
        int base = r * FSTRIDE + cq * 4;
        tile[base + 0] = v.x;
        tile[base + 1] = v.y;
        tile[base + 2] = v.z;
        tile[base + 3] = v.w;
    }
    __syncthreads();

    // Write phase: warp w covers channels c = w + 8*j; lane = spatial x.
    int lane = tid & 31;
    int w    = tid >> 5;
    #pragma unroll
    for (int j = 0; j < 12; j++) {
        int c = w + 8 * j;
        float v = tile[lane * FSTRIDE + c];
        __stcs(out + ((size_t)(b * CCH + c)) * G3 + s0 + lane, v);
    }
}

// ---------------------------------------------------------------------------
extern "C" void kernel_launch(void* const* d_in, const int* in_sizes, int n_in,
                              void* d_out, int out_size) {
    const float* coord      = (const float*)d_in[0];
    const float* feat       = (const float*)d_in[1];
    const int*   offset     = (const int*)d_in[2];
    const int*   resolution = (const int*)d_in[3];
    float*       out        = (float*)d_out;

    int n  = in_sizes[0] / 3;
    int nb = in_sizes[2];
    if (nb > BMAX) nb = BMAX;

    int acc_blocks = ((n / nb) + 31) / 32;
    if (acc_blocks < 148) acc_blocks = 148;

    for (int b = 0; b < nb; b++) {
        fused_accum_kernel<<<acc_blocks, 256>>>(coord, feat, offset, resolution, b);
        finalize_kernel<<<G3 / 32, 256>>>(out, b);
    }
}

// round 6
// speedup vs baseline: 3.1809x; 2.4379x over previous
#include <cuda_runtime.h>
#include <stdint.h>

#define VGRID   64
#define G3      (VGRID * VGRID * VGRID)       // 262144
#define BMAX    8
#define CCH     96
#define NMAX    (BMAX * 131072)               // 1048576
#define NSEG    (BMAX * G3)                   // 2097152

#define SCAN_TPB    256
#define SCAN_EPT    8
#define SCAN_CHUNK  (SCAN_TPB * SCAN_EPT)     // 2048
#define SCAN_BLOCKS (NSEG / SCAN_CHUNK)       // 1024

// All state re-derived every replay. g_cnt must be zero at entry: zero at
// module load, and the gather kernel re-zeroes it after use each replay.
__device__ int g_seg[NMAX];
__device__ int g_cnt[NSEG];
__device__ int g_pos[NSEG];      // exclusive starts; becomes ends after scatter
__device__ int g_bsum[SCAN_BLOCKS];
__device__ int g_sorted[NMAX];

// ---------------------------------------------------------------------------
// K1: per-point segment id + int histogram.
// NOTE: *50.0f (not /0.02f) is load-bearing — XLA folds the reference's
// constant division into a multiply; dividing flips floor() at boundaries.
// ---------------------------------------------------------------------------
__global__ void index_kernel(const float* __restrict__ coord,
                             const int*   __restrict__ offset,
                             const int*   __restrict__ resolution,
                             int n, int nb) {
    int p = blockIdx.x * blockDim.x + threadIdx.x;
    if (p >= n) return;

    int b = 0;
    #pragma unroll
    for (int i = 0; i < BMAX; i++)
        if (i < nb && offset[i] <= p) b++;

    float fx = coord[3 * p + 0];
    float fy = coord[3 * p + 1];
    float fz = coord[3 * p + 2];
    float vx = floorf(fx * 50.0f);
    float vy = floorf(fy * 50.0f);
    float vz = floorf(fz * 50.0f);
    float cr = (float)(resolution[b] + 1);
    float sc = __fdiv_rn(cr, (float)VGRID);
    int gx = (int)floorf(__fdiv_rn(vx, sc));
    int gy = (int)floorf(__fdiv_rn(vy, sc));
    int gz = (int)floorf(__fdiv_rn(vz, sc));
    gx = min(max(gx, 0), VGRID - 1);
    gy = min(max(gy, 0), VGRID - 1);
    gz = min(max(gz, 0), VGRID - 1);

    int sp  = (gz * VGRID + gy) * VGRID + gx;   // output spatial order (z,y,x)
    int seg = b * G3 + sp;
    g_seg[p] = seg;
    atomicAdd(&g_cnt[seg], 1);
}

// ---------------------------------------------------------------------------
// K2a: per-block reduction of 2048 counts -> g_bsum[block]
// ---------------------------------------------------------------------------
__global__ void scan_reduce_kernel() {
    __shared__ int ws[SCAN_TPB / 32];
    int tid  = threadIdx.x;
    int base = blockIdx.x * SCAN_CHUNK + tid * SCAN_EPT;
    int4 a = *(const int4*)(g_cnt + base);
    int4 c = *(const int4*)(g_cnt + base + 4);
    int s = a.x + a.y + a.z + a.w + c.x + c.y + c.z + c.w;
    #pragma unroll
    for (int d = 16; d > 0; d >>= 1) s += __shfl_down_sync(0xffffffffu, s, d);
    if ((tid & 31) == 0) ws[tid >> 5] = s;
    __syncthreads();
    if (tid == 0) {
        int t = 0;
        #pragma unroll
        for (int i = 0; i < SCAN_TPB / 32; i++) t += ws[i];
        g_bsum[blockIdx.x] = t;
    }
}

// ---------------------------------------------------------------------------
// K2b: single-block exclusive scan of the 1024 block sums (in place).
// ---------------------------------------------------------------------------
__global__ void scan_base_kernel() {
    __shared__ int win[32], wout[32];
    int tid  = threadIdx.x;          // 0..1023
    int lane = tid & 31, w = tid >> 5;
    int v = g_bsum[tid];
    int x = v;
    #pragma unroll
    for (int d = 1; d < 32; d <<= 1) {
        int y = __shfl_up_sync(0xffffffffu, x, d);
        if (lane >= d) x += y;
    }
    if (lane == 31) win[w] = x;
    __syncthreads();
    if (tid == 0) {
        int r = 0;
        #pragma unroll
        for (int i = 0; i < 32; i++) { wout[i] = r; r += win[i]; }
    }
    __syncthreads();
    g_bsum[tid] = x - v + wout[w];   // exclusive
}

// ---------------------------------------------------------------------------
// K2c: full exclusive scan; writes g_pos[i] = global exclusive prefix of cnt.
// ---------------------------------------------------------------------------
__global__ void scan_write_kernel() {
    __shared__ int win[SCAN_TPB / 32], wout[SCAN_TPB / 32];
    int tid  = threadIdx.x;
    int lane = tid & 31, w = tid >> 5;
    int base = blockIdx.x * SCAN_CHUNK + tid * SCAN_EPT;

    int4 a = *(const int4*)(g_cnt + base);
    int4 c = *(const int4*)(g_cnt + base + 4);
    int v[8] = {a.x, a.y, a.z, a.w, c.x, c.y, c.z, c.w};
    int pre[8];
    int run = 0;
    #pragma unroll
    for (int i = 0; i < 8; i++) { pre[i] = run; run += v[i]; }  // exclusive local
    int tot = run;

    int x = tot;
    #pragma unroll
    for (int d = 1; d < 32; d <<= 1) {
        int y = __shfl_up_sync(0xffffffffu, x, d);
        if (lane >= d) x += y;
    }
    if (lane == 31) win[w] = x;
    __syncthreads();
    if (tid == 0) {
        int r = 0;
        #pragma unroll
        for (int i = 0; i < SCAN_TPB / 32; i++) { wout[i] = r; r += win[i]; }
    }
    __syncthreads();
    int off = g_bsum[blockIdx.x] + wout[w] + (x - tot);

    int4 o0 = make_int4(off + pre[0], off + pre[1], off + pre[2], off + pre[3]);
    int4 o1 = make_int4(off + pre[4], off + pre[5], off + pre[6], off + pre[7]);
    *(int4*)(g_pos + base)     = o0;
    *(int4*)(g_pos + base + 4) = o1;
}

// ---------------------------------------------------------------------------
// K3: scatter point ids into contiguous per-voxel runs.
// Mutates g_pos: after this, g_pos[v] == end of run v (start = end - cnt).
// ---------------------------------------------------------------------------
__global__ void scatter_kernel(int n) {
    int p = blockIdx.x * blockDim.x + threadIdx.x;
    if (p >= n) return;
    int seg = g_seg[p];
    int pos = atomicAdd(&g_pos[seg], 1);
    g_sorted[pos] = p;
}

// ---------------------------------------------------------------------------
// K4: gather + mean + transpose + output. One block per 32 voxels.
// 8 threads/voxel; each owns 12 channels (3 float4 accumulators), loops over
// the voxel's points reading feat rows in coalesced 128B groups. No float
// atomics anywhere. Re-zeroes g_cnt for the next replay.
// ---------------------------------------------------------------------------
#define FSTRIDE 97

__global__ void gather_kernel(const float* __restrict__ feat,
                              float* __restrict__ out) {
    __shared__ float tile[32 * FSTRIDE];
    __shared__ int   s_start[32], s_k[32];
    __shared__ float s_rinv[32];

    int vbase = blockIdx.x * 32;             // global seg base; one b per block
    int tid   = threadIdx.x;

    if (tid < 32) {
        int v = vbase + tid;
        int k = g_cnt[v];
        int e = g_pos[v];                    // end after scatter
        s_k[tid]     = k;
        s_start[tid] = e - k;
        s_rinv[tid]  = (k > 0) ? __fdiv_rn(1.0f, (float)k) : 0.0f;
        g_cnt[v] = 0;                        // reset for next replay
    }
    __syncthreads();

    int r = tid >> 3;                        // local voxel 0..31
    int g = tid & 7;                         // float4 slot 0..7
    int k    = s_k[r];
    int st   = s_start[r];
    float ri = s_rinv[r];

    float4 a0 = make_float4(0.f, 0.f, 0.f, 0.f);
    float4 a1 = a0, a2 = a0;
    for (int i = 0; i < k; i++) {
        int pid = g_sorted[st + i];
        const float4* frow = (const float4*)(feat + (size_t)pid * CCH);
        float4 f0 = __ldcs(frow + g);
        float4 f1 = __ldcs(frow + g + 8);
        float4 f2 = __ldcs(frow + g + 16);
        a0.x += f0.x; a0.y += f0.y; a0.z += f0.z; a0.w += f0.w;
        a1.x += f1.x; a1.y += f1.y; a1.z += f1.z; a1.w += f1.w;
        a2.x += f2.x; a2.y += f2.y; a2.z += f2.z; a2.w += f2.w;
    }
    a0.x *= ri; a0.y *= ri; a0.z *= ri; a0.w *= ri;
    a1.x *= ri; a1.y *= ri; a1.z *= ri; a1.w *= ri;
    a2.x *= ri; a2.y *= ri; a2.z *= ri; a2.w *= ri;

    int base = r * FSTRIDE + g * 4;
    tile[base +  0] = a0.x; tile[base +  1] = a0.y;
    tile[base +  2] = a0.z; tile[base +  3] = a0.w;
    tile[base + 32] = a1.x; tile[base + 33] = a1.y;
    tile[base + 34] = a1.z; tile[base + 35] = a1.w;
    tile[base + 64] = a2.x; tile[base + 65] = a2.y;
    tile[base + 66] = a2.z; tile[base + 67] = a2.w;
    __syncthreads();

    // Transposed write: warp w -> channels c = w + 8j, lane -> spatial x.
    int lane = tid & 31;
    int w    = tid >> 5;
    int b    = vbase >> 18;                  // / G3
    int sp0  = vbase & (G3 - 1);
    #pragma unroll
    for (int j = 0; j < 12; j++) {
        int c = w + 8 * j;
        __stcs(out + ((size_t)(b * CCH + c)) * G3 + sp0 + lane,
               tile[lane * FSTRIDE + c]);
    }
}

// ---------------------------------------------------------------------------
extern "C" void kernel_launch(void* const* d_in, const int* in_sizes, int n_in,
                              void* d_out, int out_size) {
    const float* coord      = (const float*)d_in[0];
    const float* feat       = (const float*)d_in[1];
    const int*   offset     = (const int*)d_in[2];
    const int*   resolution = (const int*)d_in[3];
    float*       out        = (float*)d_out;

    int n  = in_sizes[0] / 3;
    int nb = in_sizes[2];
    if (nb > BMAX) nb = BMAX;

    index_kernel<<<(n + 255) / 256, 256>>>(coord, offset, resolution, n, nb);
    scan_reduce_kernel<<<SCAN_BLOCKS, SCAN_TPB>>>();
    scan_base_kernel<<<1, SCAN_BLOCKS>>>();
    scan_write_kernel<<<SCAN_BLOCKS, SCAN_TPB>>>();
    scatter_kernel<<<(n + 255) / 256, 256>>>(n);
    gather_kernel<<<nb * (G3 / 32), 256>>>(feat, out);
}